// round 15
// baseline (speedup 1.0000x reference)
#include <cuda_runtime.h>
#include <cstdint>

#define Bn 8192
#define Fn 4096
#define Kn 64
#define MT 32            // rows per CTA -> 256 CTAs, 2 resident per SM
#define KC 64            // F-depth per stage (64 iterations)
#define NT 256           // 8 warps: 2M x 2N x 2F
#define STAGES 3
#define NTILES (Fn / KC) // 64

#define XROWB 272        // X row stride (64 f32 + 16B pad)
#define VROWB 288        // V row stride (64 f32 + 32B pad)

// ---- smem layout (bytes) ----
#define SM_XSQ    0                     // 4 x 32 f32 = 512
#define SM_RED    512                   // 2 x 32 f32 = 256
#define SM_TILES  1024
#define SLOT_X    0                     // 32 x 272 = 8704
#define SLOT_V    8704                  // 64 x 288 = 18432
#define SLOT_SZ   27136
#define SMEM_TOTAL (SM_TILES + STAGES * SLOT_SZ)   // 82432 -> 2 CTAs/SM

__device__ float d_s[Fn];
__device__ float d_vt[Kn * Fn];    // v^T rna-tf32, f-permuted [f0,f4,f1,f5,f2,f6,f3,f7]

__device__ __forceinline__ uint32_t smem_u32(const void* p) {
    uint32_t a;
    asm("{ .reg .u64 t; cvta.to.shared.u64 t, %1; cvt.u32.u64 %0, t; }" : "=r"(a) : "l"(p));
    return a;
}
#define CP16(sa, gp) \
    asm volatile("cp.async.cg.shared.global [%0], [%1], 16;" :: "r"(sa), "l"(gp) : "memory")
#define CP_COMMIT() asm volatile("cp.async.commit_group;" ::: "memory")

__device__ __forceinline__ uint32_t to_tf32(float f) {
    uint32_t u;
    asm("cvt.rna.tf32.f32 %0, %1;" : "=r"(u) : "f"(f));
    return u;
}
__device__ __forceinline__ void mma_tf32(float* c, const uint32_t* a,
                                         uint32_t b0, uint32_t b1) {
    asm volatile("mma.sync.aligned.m16n8k8.row.col.f32.tf32.tf32.f32 "
                 "{%0,%1,%2,%3}, {%4,%5,%6,%7}, {%8,%9}, {%0,%1,%2,%3};"
                 : "+f"(c[0]), "+f"(c[1]), "+f"(c[2]), "+f"(c[3])
                 : "r"(a[0]), "r"(a[1]), "r"(a[2]), "r"(a[3]), "r"(b0), "r"(b1));
}
#define LDMATRIX4(r0, r1, r2, r3, addr) \
    asm volatile("ldmatrix.sync.aligned.m8n8.x4.shared.b16 {%0,%1,%2,%3}, [%4];" \
                 : "=r"(r0), "=r"(r1), "=r"(r2), "=r"(r3) : "r"(addr))

// ===== prep: transpose v (rna-tf32) with paired-k f-permutation + s table =====
__global__ void prep_v(const float* __restrict__ v) {
    __shared__ float tile[32][65];
    const int f0 = blockIdx.x * 32;
    const int tid = threadIdx.x;
    for (int i = tid; i < 32 * 64; i += 256) {
        int fr = i >> 6, k = i & 63;
        tile[fr][k] = v[(size_t)(f0 + fr) * Kn + k];
    }
    __syncthreads();
    for (int i = tid; i < 32 * 64; i += 256) {
        int k = i >> 5, fr = i & 31;
        int f = f0 + fr;
        int g = f & 7;
        int pos = (f & ~7) + ((g & 3) << 1) + (g >> 2);   // [f0,f4,f1,f5,f2,f6,f3,f7]
        d_vt[(size_t)k * Fn + pos] = __uint_as_float(to_tf32(tile[fr][k]));
    }
    const int fr = tid >> 3, q = tid & 7;
    float t = 0.f;
#pragma unroll
    for (int j = 0; j < 8; j++) {
        float val = tile[fr][q * 8 + j];
        t = fmaf(val, val, t);
    }
    t += __shfl_xor_sync(0xffffffffu, t, 1);
    t += __shfl_xor_sync(0xffffffffu, t, 2);
    t += __shfl_xor_sync(0xffffffffu, t, 4);
    if (q == 0) d_s[f0 + fr] = t;
}

// ================= main kernel =================
__device__ __forceinline__ void load_stage(const float* __restrict__ x, int row0,
                                           int t, int slot, uint32_t sb) {
    const int f0 = t * KC;
    const uint32_t base = sb + SM_TILES + slot * SLOT_SZ;
    const int tid = threadIdx.x;
#pragma unroll
    for (int j = 0; j < 2; j++) {   // X: 32 rows x 16 chunks of 16B = 512
        const int idx = tid + 256 * j;
        const int r = idx >> 4, c = idx & 15;
        CP16(base + SLOT_X + (uint32_t)(r * XROWB + c * 16),
             x + (size_t)(row0 + r) * Fn + f0 + c * 4);
    }
#pragma unroll
    for (int j = 0; j < 4; j++) {   // V: 64 rows x 16 chunks of 16B = 1024
        const int idx = tid + 256 * j;
        const int r = idx >> 4, c = idx & 15;
        CP16(base + SLOT_V + (uint32_t)(r * VROWB + c * 16),
             d_vt + (size_t)r * Fn + f0 + c * 4);
    }
}

__global__ void __launch_bounds__(NT, 2) fm_kernel(const float* __restrict__ x,
                                                   float* __restrict__ out) {
    extern __shared__ char smem[];
    const uint32_t sb = smem_u32(smem);
    const int tid = threadIdx.x;
    const int warp = tid >> 5, lane = tid & 31;
    const int wm = warp >> 2;          // 0..1 -> M offset 16*wm
    const int wn = (warp >> 1) & 1;    // 0..1 -> N offset 32*wn
    const int kf = warp & 1;           // 0..1 -> f-half (32 f per stage)
    const int lr = lane >> 2, lc = lane & 3;
    const int row0 = blockIdx.x * MT;

    load_stage(x, row0, 0, 0, sb); CP_COMMIT();
    load_stage(x, row0, 1, 1, sb); CP_COMMIT();

    float acc[4][4];   // [nt][c]
#pragma unroll
    for (int n = 0; n < 4; n++)
#pragma unroll
        for (int c = 0; c < 4; c++) acc[n][c] = 0.f;
    float xs[2] = {0.f, 0.f};

    const uint32_t a_lm = (uint32_t)((16 * wm + (lane & 7) + 8 * ((lane >> 3) & 1)) * XROWB
                                     + (lane >> 4) * 16 + kf * 128);
    const uint32_t boff = (uint32_t)((32 * wn + lr) * VROWB + lc * 8 + kf * 128);
    const float* s_base = d_s + 32 * kf + lc;

    int slot = 0;
    for (int t = 0; t < NTILES; t++) {
        if (t + STAGES - 1 < NTILES) asm volatile("cp.async.wait_group %0;" :: "n"(STAGES - 2) : "memory");
        else                         asm volatile("cp.async.wait_group 0;" ::: "memory");
        __syncthreads();
        if (t + STAGES - 1 < NTILES) {
            int ps = slot + 2; if (ps >= STAGES) ps -= STAGES;
            load_stage(x, row0, t + STAGES - 1, ps, sb);
            CP_COMMIT();
        }

        const uint32_t tb = sb + SM_TILES + slot * SLOT_SZ;
        const uint32_t xa = tb + SLOT_X + a_lm;
        const char* vbp = smem + SM_TILES + slot * SLOT_SZ + SLOT_V + boff;
        const float* srow = s_base + t * KC;

#pragma unroll
        for (int j = 0; j < 4; j++) {
            uint32_t ar[4];
            LDMATRIX4(ar[0], ar[1], ar[2], ar[3], xa + j * 32);

            if ((j & 1) == wn) {   // distributed x^2*s on raw f32 bits
                float s0 = __ldg(srow + j * 8);
                float s1 = __ldg(srow + j * 8 + 4);
                float a0 = __uint_as_float(ar[0]), a1 = __uint_as_float(ar[1]);
                float a2 = __uint_as_float(ar[2]), a3 = __uint_as_float(ar[3]);
                xs[0] = fmaf(a0 * a0, s0, xs[0]);
                xs[0] = fmaf(a2 * a2, s1, xs[0]);
                xs[1] = fmaf(a1 * a1, s0, xs[1]);
                xs[1] = fmaf(a3 * a3, s1, xs[1]);
            }
            ar[0] = to_tf32(__uint_as_float(ar[0]));
            ar[1] = to_tf32(__uint_as_float(ar[1]));
            ar[2] = to_tf32(__uint_as_float(ar[2]));
            ar[3] = to_tf32(__uint_as_float(ar[3]));

#pragma unroll
            for (int nt = 0; nt < 4; nt++) {
                float2 b = *(const float2*)(vbp + nt * (8 * VROWB) + j * 32);
                mma_tf32(acc[nt], ar, __float_as_uint(b.x), __float_as_uint(b.y));
            }
        }
        if (++slot == STAGES) slot = 0;
    }

    // ---- epilogue ----
    float* xsq_s = (float*)(smem + SM_XSQ);
#pragma unroll
    for (int i = 0; i < 2; i++) {
        float p = xs[i];
        p += __shfl_xor_sync(0xffffffffu, p, 1);
        p += __shfl_xor_sync(0xffffffffu, p, 2);
        if (lc == 0) xsq_s[(2 * kf + wn) * 32 + 16 * wm + 8 * i + lr] = p;
    }

    // combine f-half partial accumulators exactly in fp32 (reuse tile region)
    __syncthreads();   // all tile reads done; safe to overwrite
    float* khb = (float*)(smem + SM_TILES);
    const int pid = 2 * wm + wn;
    if (kf == 1) {
        float4* dst = (float4*)(khb + (pid * 32 + lane) * 16);
#pragma unroll
        for (int n = 0; n < 4; n++)
            dst[n] = make_float4(acc[n][0], acc[n][1], acc[n][2], acc[n][3]);
    }
    __syncthreads();

    float* red = (float*)(smem + SM_RED);
    if (kf == 0) {
        const float4* src = (const float4*)(khb + (pid * 32 + lane) * 16);
        float p0 = 0.f, p1 = 0.f;
#pragma unroll
        for (int n = 0; n < 4; n++) {
            float4 o = src[n];
            float v0 = acc[n][0] + o.x;
            float v1 = acc[n][1] + o.y;
            float v2 = acc[n][2] + o.z;
            float v3 = acc[n][3] + o.w;
            p0 += v0 * v0 + v1 * v1;
            p1 += v2 * v2 + v3 * v3;
        }
        p0 += __shfl_xor_sync(0xffffffffu, p0, 1);
        p0 += __shfl_xor_sync(0xffffffffu, p0, 2);
        p1 += __shfl_xor_sync(0xffffffffu, p1, 1);
        p1 += __shfl_xor_sync(0xffffffffu, p1, 2);
        if (lc == 0) {
            red[wn * 32 + 16 * wm + lr] = p0;
            red[wn * 32 + 16 * wm + lr + 8] = p1;
        }
    }
    __syncthreads();

    if (tid < MT) {
        float tot = red[tid] + red[32 + tid];
        float xst = xsq_s[tid] + xsq_s[32 + tid] + xsq_s[64 + tid] + xsq_s[96 + tid];
        out[row0 + tid] = 0.5f * (tot - xst);
    }
}

extern "C" void kernel_launch(void* const* d_in, const int* in_sizes, int n_in,
                              void* d_out, int out_size) {
    const float* x = (const float*)d_in[0];   // [8192, 4096]
    const float* v = (const float*)d_in[1];   // [4096, 64]
    float* out = (float*)d_out;               // [8192, 1]

    cudaFuncSetAttribute(fm_kernel, cudaFuncAttributeMaxDynamicSharedMemorySize, SMEM_TOTAL);
    prep_v<<<Fn / 32, 256>>>(v);
    fm_kernel<<<Bn / MT, NT, SMEM_TOTAL>>>(x, out);
}

// round 16
// speedup vs baseline: 1.4720x; 1.4720x over previous
#include <cuda_runtime.h>
#include <cstdint>

#define Bn 8192
#define Fn 4096
#define Kn 64
#define MT 64            // rows per CTA -> 128 CTAs
#define KC 128           // F-depth per stage (32 iterations)
#define NT 640           // 16 consumer warps (2M x 2N x 4F) + 4 producer warps
#define NCONS 512
#define STAGES 3
#define NTILES (Fn / KC) // 32

#define XROWB 528        // X row stride (128 f32 + 16B pad)
#define VROWB 544        // V row stride (128 f32 + 32B pad)

// ---- smem layout (bytes) ----
#define SM_BAR    0                     // 3 x (full,empty) mbarrier pairs, 16B each
#define SM_XSQ    64                    // 8 x 64 f32 = 2048
#define SM_RED    2112                  // 2 x 64 f32 = 512
#define SM_TILES  2688
#define SLOT_X    0                     // 64 x 528 = 33792
#define SLOT_V    33792                 // 64 x 544 = 34816
#define SLOT_SZ   68608
#define SMEM_TOTAL (SM_TILES + STAGES * SLOT_SZ)   // 208512

__device__ float d_s[Fn];
__device__ float d_vt[Kn * Fn];    // v^T rna-tf32, f-permuted [f0,f4,f1,f5,f2,f6,f3,f7]

__device__ __forceinline__ uint32_t smem_u32(const void* p) {
    uint32_t a;
    asm("{ .reg .u64 t; cvta.to.shared.u64 t, %1; cvt.u32.u64 %0, t; }" : "=r"(a) : "l"(p));
    return a;
}
#define CP16(sa, gp) \
    asm volatile("cp.async.cg.shared.global [%0], [%1], 16;" :: "r"(sa), "l"(gp) : "memory")
#define MBAR_INIT(addr, cnt) \
    asm volatile("mbarrier.init.shared.b64 [%0], %1;" :: "r"(addr), "r"(cnt) : "memory")
#define MBAR_ARRIVE(addr) \
    asm volatile("mbarrier.arrive.shared.b64 _, [%0];" :: "r"(addr) : "memory")
#define CPASYNC_MBAR_ARRIVE(addr) \
    asm volatile("cp.async.mbarrier.arrive.noinc.shared.b64 [%0];" :: "r"(addr) : "memory")
#define MBAR_WAIT(addr, par) do {                                              \
    uint32_t _m = (addr); uint32_t _p = (par); uint32_t _d;                    \
    asm volatile("{\n\t.reg .pred p;\n\t"                                      \
        "mbarrier.try_wait.parity.acquire.cta.shared::cta.b64 p, [%1], %2;\n\t"\
        "selp.b32 %0, 1, 0, p;\n\t}"                                           \
        : "=r"(_d) : "r"(_m), "r"(_p) : "memory");                             \
    if (!_d) {                                                                 \
        asm volatile("{\n\t.reg .pred P1;\n\t"                                 \
        "WL_%=:\n\t"                                                           \
        "mbarrier.try_wait.parity.acquire.cta.shared::cta.b64 P1, [%0], %1, 0x989680;\n\t" \
        "@P1 bra.uni WD_%=;\n\t"                                               \
        "bra.uni WL_%=;\n\t"                                                   \
        "WD_%=:\n\t}" :: "r"(_m), "r"(_p) : "memory");                         \
    }                                                                          \
} while (0)
#define BAR_CONS() asm volatile("bar.sync 1, %0;" :: "n"(NCONS) : "memory")

__device__ __forceinline__ uint32_t to_tf32(float f) {
    uint32_t u;
    asm("cvt.rna.tf32.f32 %0, %1;" : "=r"(u) : "f"(f));
    return u;
}
__device__ __forceinline__ void mma_tf32(float* c, const uint32_t* a,
                                         uint32_t b0, uint32_t b1) {
    asm volatile("mma.sync.aligned.m16n8k8.row.col.f32.tf32.tf32.f32 "
                 "{%0,%1,%2,%3}, {%4,%5,%6,%7}, {%8,%9}, {%0,%1,%2,%3};"
                 : "+f"(c[0]), "+f"(c[1]), "+f"(c[2]), "+f"(c[3])
                 : "r"(a[0]), "r"(a[1]), "r"(a[2]), "r"(a[3]), "r"(b0), "r"(b1));
}
#define LDMATRIX4(r0, r1, r2, r3, addr) \
    asm volatile("ldmatrix.sync.aligned.m8n8.x4.shared.b16 {%0,%1,%2,%3}, [%4];" \
                 : "=r"(r0), "=r"(r1), "=r"(r2), "=r"(r3) : "r"(addr))

// ===== prep: transpose v (rna-tf32) with paired-k f-permutation + s table =====
__global__ void prep_v(const float* __restrict__ v) {
    __shared__ float tile[32][65];
    const int f0 = blockIdx.x * 32;
    const int tid = threadIdx.x;
    for (int i = tid; i < 32 * 64; i += 256) {
        int fr = i >> 6, k = i & 63;
        tile[fr][k] = v[(size_t)(f0 + fr) * Kn + k];
    }
    __syncthreads();
    for (int i = tid; i < 32 * 64; i += 256) {
        int k = i >> 5, fr = i & 31;
        int f = f0 + fr;
        int g = f & 7;
        int pos = (f & ~7) + ((g & 3) << 1) + (g >> 2);   // [f0,f4,f1,f5,f2,f6,f3,f7]
        d_vt[(size_t)k * Fn + pos] = __uint_as_float(to_tf32(tile[fr][k]));
    }
    const int fr = tid >> 3, q = tid & 7;
    float t = 0.f;
#pragma unroll
    for (int j = 0; j < 8; j++) {
        float val = tile[fr][q * 8 + j];
        t = fmaf(val, val, t);
    }
    t += __shfl_xor_sync(0xffffffffu, t, 1);
    t += __shfl_xor_sync(0xffffffffu, t, 2);
    t += __shfl_xor_sync(0xffffffffu, t, 4);
    if (q == 0) d_s[f0 + fr] = t;
}

// ================= main kernel =================
__global__ void __launch_bounds__(NT, 1) fm_kernel(const float* __restrict__ x,
                                                   float* __restrict__ out) {
    extern __shared__ char smem[];
    const uint32_t sb = smem_u32(smem);
    const int tid = threadIdx.x;
    const int warp = tid >> 5, lane = tid & 31;
    const int row0 = blockIdx.x * MT;

    // mbarrier init: full count = 128 producer async arrivals; empty = 512 consumers
    if (tid == 0) {
        for (int s = 0; s < STAGES; s++) {
            MBAR_INIT(sb + SM_BAR + 16 * s, 128);      // full
            MBAR_INIT(sb + SM_BAR + 16 * s + 8, NCONS); // empty
        }
    }
    __syncthreads();

    if (warp >= 16) {
        // ================= producer warps (16..19) =================
        const int pt = tid - NCONS;     // 0..127
        int pslot = 0, pphase = 1;
        for (int t = 0; t < NTILES; t++) {
            MBAR_WAIT(sb + SM_BAR + 16 * pslot + 8, pphase);   // wait empty
            const int f0 = t * KC;
            const uint32_t base = sb + SM_TILES + pslot * SLOT_SZ;
#pragma unroll
            for (int j = 0; j < 16; j++) {      // X: 2048 chunks of 16B
                const int idx = pt + 128 * j;
                const int r = idx >> 5, c = idx & 31;
                CP16(base + SLOT_X + (uint32_t)(r * XROWB + c * 16),
                     x + (size_t)(row0 + r) * Fn + f0 + c * 4);
            }
#pragma unroll
            for (int j = 0; j < 16; j++) {      // V: 2048 chunks of 16B
                const int idx = pt + 128 * j;
                const int r = idx >> 5, c = idx & 31;
                CP16(base + SLOT_V + (uint32_t)(r * VROWB + c * 16),
                     d_vt + (size_t)r * Fn + f0 + c * 4);
            }
            CPASYNC_MBAR_ARRIVE(sb + SM_BAR + 16 * pslot);     // arrive full on completion
            if (++pslot == STAGES) { pslot = 0; pphase ^= 1; }
        }
        return;
    }

    // ================= consumer warps (0..15): R14 math =================
    const int wm = warp >> 3;          // 0..1 -> M offset 32*wm (2 m16 tiles)
    const int wn = (warp >> 2) & 1;    // 0..1 -> N offset 32*wn (4 n8 tiles)
    const int kf = warp & 3;           // 0..3 -> f-quarter (32 f per stage)
    const int lr = lane >> 2, lc = lane & 3;

    float acc[2][4][4];   // [mt][nt][c]
#pragma unroll
    for (int m = 0; m < 2; m++)
#pragma unroll
        for (int n = 0; n < 4; n++)
#pragma unroll
            for (int c = 0; c < 4; c++) acc[m][n][c] = 0.f;
    float xs[2][2] = {{0.f, 0.f}, {0.f, 0.f}};

    const uint32_t a_lm = (uint32_t)((32 * wm + (lane & 7) + 8 * ((lane >> 3) & 1)) * XROWB
                                     + (lane >> 4) * 16 + kf * 128);
    const uint32_t boff = (uint32_t)((32 * wn + lr) * VROWB + lc * 8 + kf * 128);
    const float* s_base = d_s + 32 * kf + lc;

    int slot = 0, phase = 0;
    for (int t = 0; t < NTILES; t++) {
        MBAR_WAIT(sb + SM_BAR + 16 * slot, phase);   // wait full (acquire)

        const uint32_t xa = sb + SM_TILES + slot * SLOT_SZ + SLOT_X + a_lm;
        const char* vbp = smem + SM_TILES + slot * SLOT_SZ + SLOT_V + boff;
        const float* srow = s_base + t * KC;

#pragma unroll
        for (int j = 0; j < 4; j++) {
            uint32_t ar[2][4];
#pragma unroll
            for (int mt = 0; mt < 2; mt++) {
                LDMATRIX4(ar[mt][0], ar[mt][1], ar[mt][2], ar[mt][3],
                          xa + mt * (16 * XROWB) + j * 32);
            }
            if ((j & 1) == wn) {   // distributed x^2*s on raw f32 bits
                float s0 = __ldg(srow + j * 8);
                float s1 = __ldg(srow + j * 8 + 4);
#pragma unroll
                for (int mt = 0; mt < 2; mt++) {
                    float a0 = __uint_as_float(ar[mt][0]), a1 = __uint_as_float(ar[mt][1]);
                    float a2 = __uint_as_float(ar[mt][2]), a3 = __uint_as_float(ar[mt][3]);
                    xs[mt][0] = fmaf(a0 * a0, s0, xs[mt][0]);
                    xs[mt][0] = fmaf(a2 * a2, s1, xs[mt][0]);
                    xs[mt][1] = fmaf(a1 * a1, s0, xs[mt][1]);
                    xs[mt][1] = fmaf(a3 * a3, s1, xs[mt][1]);
                }
            }
#pragma unroll
            for (int mt = 0; mt < 2; mt++) {
                ar[mt][0] = to_tf32(__uint_as_float(ar[mt][0]));
                ar[mt][1] = to_tf32(__uint_as_float(ar[mt][1]));
                ar[mt][2] = to_tf32(__uint_as_float(ar[mt][2]));
                ar[mt][3] = to_tf32(__uint_as_float(ar[mt][3]));
            }
#pragma unroll
            for (int nt = 0; nt < 4; nt++) {
                float2 b = *(const float2*)(vbp + nt * (8 * VROWB) + j * 32);
                mma_tf32(acc[0][nt], ar[0], __float_as_uint(b.x), __float_as_uint(b.y));
                mma_tf32(acc[1][nt], ar[1], __float_as_uint(b.x), __float_as_uint(b.y));
            }
        }
        MBAR_ARRIVE(sb + SM_BAR + 16 * slot + 8);    // release stage
        if (++slot == STAGES) { slot = 0; phase ^= 1; }
    }

    // ---- epilogue (consumers only; named barrier over 512 threads) ----
    float* xsq_s = (float*)(smem + SM_XSQ);
#pragma unroll
    for (int mt = 0; mt < 2; mt++)
#pragma unroll
        for (int i = 0; i < 2; i++) {
            float p = xs[mt][i];
            p += __shfl_xor_sync(0xffffffffu, p, 1);
            p += __shfl_xor_sync(0xffffffffu, p, 2);
            if (lc == 0)
                xsq_s[(2 * kf + wn) * 64 + 32 * wm + 16 * mt + 8 * i + lr] = p;
        }

    // combine f-quarter partial accumulators exactly in fp32 (reuse tile region)
    BAR_CONS();   // all consumers done reading tiles (producers exited)
    float* scr = (float*)(smem + SM_TILES) + warp * 1024 + lane * 32;
#pragma unroll
    for (int mt = 0; mt < 2; mt++)
#pragma unroll
        for (int nt = 0; nt < 4; nt++)
#pragma unroll
            for (int c = 0; c < 4; c++)
                scr[mt * 16 + nt * 4 + c] = acc[mt][nt][c];
    BAR_CONS();

    float* red = (float*)(smem + SM_RED);
    if (kf == 0) {
        const float* p1s = scr + 1 * 1024;
        const float* p2s = scr + 2 * 1024;
        const float* p3s = scr + 3 * 1024;
#pragma unroll
        for (int mt = 0; mt < 2; mt++) {
            float p0 = 0.f, p1 = 0.f;
#pragma unroll
            for (int nt = 0; nt < 4; nt++) {
#pragma unroll
                for (int c = 0; c < 4; c++) {
                    int idx = mt * 16 + nt * 4 + c;
                    float v = acc[mt][nt][c] + p1s[idx] + p2s[idx] + p3s[idx];
                    if (c < 2) p0 += v * v; else p1 += v * v;
                }
            }
            p0 += __shfl_xor_sync(0xffffffffu, p0, 1);
            p0 += __shfl_xor_sync(0xffffffffu, p0, 2);
            p1 += __shfl_xor_sync(0xffffffffu, p1, 1);
            p1 += __shfl_xor_sync(0xffffffffu, p1, 2);
            if (lc == 0) {
                int r = 32 * wm + 16 * mt + lr;
                red[wn * 64 + r] = p0;
                red[wn * 64 + r + 8] = p1;
            }
        }
    }
    BAR_CONS();

    if (tid < MT) {
        float tot = red[tid] + red[64 + tid];
        float xst = 0.f;
#pragma unroll
        for (int q = 0; q < 8; q++) xst += xsq_s[q * 64 + tid];
        out[row0 + tid] = 0.5f * (tot - xst);
    }
}

extern "C" void kernel_launch(void* const* d_in, const int* in_sizes, int n_in,
                              void* d_out, int out_size) {
    const float* x = (const float*)d_in[0];   // [8192, 4096]
    const float* v = (const float*)d_in[1];   // [4096, 64]
    float* out = (float*)d_out;               // [8192, 1]

    cudaFuncSetAttribute(fm_kernel, cudaFuncAttributeMaxDynamicSharedMemorySize, SMEM_TOTAL);
    prep_v<<<Fn / 32, 256>>>(v);
    fm_kernel<<<Bn / MT, NT, SMEM_TOTAL>>>(x, out);
}